// round 1
// baseline (speedup 1.0000x reference)
#include <cuda_runtime.h>
#include <math.h>

#define NE    50000
#define DIM   200
#define BATCH 1024
#define EMAX  400000
#define RELD  40000   // DIM*DIM

// ---------------- scratch (device globals; no allocation allowed) ----------
__device__ float g_U [NE*DIM];
__device__ float g_V [NE*DIM];
__device__ float g_H [NE*DIM];
__device__ float g_X1[NE*DIM];
__device__ float g_X2[NE*DIM];
__device__ float g_MP[NE*DIM];
__device__ float g_HR[BATCH*DIM];
__device__ float g_NMASK[2*NE];
__device__ float g_NEWEDGE[EMAX];
__device__ int   g_rp_adj[NE+1];
__device__ int   g_rp_rw [NE+1];

// ---------------- helpers ----------------
__device__ __forceinline__ float gate_fn(float logits, float u) {
    const float bias = 1e-4f;
    float eps = (2.f*bias - 1.f)*u + (1.f - bias);
    float t = 2.f*(logf(eps) - log1pf(-eps) + logits);
    return 1.f/(1.f + expf(-t));
}

__device__ __forceinline__ float warp_sum(float v) {
    #pragma unroll
    for (int o = 16; o; o >>= 1) v += __shfl_xor_sync(0xffffffffu, v, o);
    return v;
}

// ---------------- rowptr from sorted COO rows (lower_bound) ----------------
__global__ void rowptr_k(const int* __restrict__ row, int nnz, int* __restrict__ rowptr) {
    int n = blockIdx.x*blockDim.x + threadIdx.x;
    if (n > NE) return;
    int lo = 0, hi = nnz;
    while (lo < hi) { int mid = (lo+hi) >> 1; if (row[mid] < n) lo = mid+1; else hi = mid; }
    rowptr[n] = lo;
}

// ---------------- C[M x 200] = act(A[M x 200] @ B[200 x 200] + bias) -------
// tile: 64 rows x full 200 cols, K tiled by 40
__global__ void gemm_k200(const float* __restrict__ A, const float* __restrict__ B,
                          const float* __restrict__ bias, float* __restrict__ C,
                          int M, int do_relu) {
    __shared__ float As[64][40];
    __shared__ float Bs[40][224];
    int bm = blockIdx.x;
    int tid = threadIdx.x;
    int lane = tid & 31, tm = tid >> 5;
    float acc[8][7];
    #pragma unroll
    for (int i = 0; i < 8; i++)
        #pragma unroll
        for (int u = 0; u < 7; u++) acc[i][u] = 0.f;

    for (int k0 = 0; k0 < 200; k0 += 40) {
        for (int t = tid; t < 64*40; t += 256) {
            int r = t/40, c = t%40;
            int gm = bm*64 + r;
            As[r][c] = (gm < M) ? A[(size_t)gm*DIM + k0 + c] : 0.f;
        }
        for (int t = tid; t < 40*224; t += 256) {
            int r = t/224, c = t%224;
            Bs[r][c] = (c < 200) ? B[(size_t)(k0+r)*DIM + c] : 0.f;
        }
        __syncthreads();
        #pragma unroll
        for (int k = 0; k < 40; k++) {
            float bf[7];
            #pragma unroll
            for (int u = 0; u < 7; u++) bf[u] = Bs[k][lane + 32*u];
            #pragma unroll
            for (int i = 0; i < 8; i++) {
                float a = As[tm*8+i][k];
                #pragma unroll
                for (int u = 0; u < 7; u++) acc[i][u] = fmaf(a, bf[u], acc[i][u]);
            }
        }
        __syncthreads();
    }
    #pragma unroll
    for (int i = 0; i < 8; i++) {
        int gm = bm*64 + tm*8 + i;
        if (gm >= M) continue;
        #pragma unroll
        for (int u = 0; u < 7; u++) {
            int j = lane + 32*u;
            if (j < 200) {
                float v = acc[i][u] + (bias ? bias[j] : 0.f);
                if (do_relu) v = fmaxf(v, 0.f);
                C[(size_t)gm*DIM + j] = v;
            }
        }
    }
}

// ---------------- node gate: logits = H[n,:] . W2 + b2 ; mask = gate -------
__global__ void node_gate_k(const float* __restrict__ H, const float* __restrict__ W2,
                            const float* __restrict__ b2, const float* __restrict__ eps,
                            float* __restrict__ mask) {
    int w = (blockIdx.x*blockDim.x + threadIdx.x) >> 5;
    int lane = threadIdx.x & 31;
    if (w >= NE) return;
    float acc = 0.f;
    const float* hr = H + (size_t)w*DIM;
    #pragma unroll
    for (int u = 0; u < 7; u++) {
        int j = lane + 32*u;
        if (j < 200) acc = fmaf(hr[j], W2[j], acc);
    }
    acc = warp_sum(acc);
    if (lane == 0) mask[w] = gate_fn(acc + b2[0], eps[w]);
}

// ---------------- edge gate (i=1 only): he=relu(U[r]+V[c]); new_edge -------
__global__ void edge_gate_k(const int* __restrict__ row, const int* __restrict__ col,
                            const float* __restrict__ adj_val,
                            const float* __restrict__ W2, const float* __restrict__ b2,
                            const float* __restrict__ eps, float* __restrict__ new_edge,
                            int E) {
    int e = (blockIdx.x*blockDim.x + threadIdx.x) >> 5;
    int lane = threadIdx.x & 31;
    if (e >= E) return;
    int r = row[e], c = col[e];
    const float* ur = g_U + (size_t)r*DIM;
    const float* vr = g_V + (size_t)c*DIM;
    float acc = 0.f;
    #pragma unroll
    for (int u = 0; u < 7; u++) {
        int j = lane + 32*u;
        if (j < 200) {
            float he = fmaxf(ur[j] + vr[j], 0.f);
            acc = fmaf(he, W2[j], acc);
        }
    }
    acc = warp_sum(acc);
    if (lane == 0) new_edge[e] = adj_val[e] * gate_fn(acc + b2[0], eps[e]);
}

// ---------------- CSR SpMM: y[r,:] = sum val * x[col,:] (warp per row) -----
__global__ void spmm_k(const int* __restrict__ rowptr, const int* __restrict__ col,
                       const float* __restrict__ val, const float* __restrict__ x,
                       float* __restrict__ y) {
    int r = (blockIdx.x*blockDim.x + threadIdx.x) >> 5;
    int lane = threadIdx.x & 31;
    if (r >= NE) return;
    float acc[7];
    #pragma unroll
    for (int u = 0; u < 7; u++) acc[u] = 0.f;
    int s = rowptr[r], e = rowptr[r+1];
    for (int idx = s; idx < e; idx++) {
        int c = __ldg(&col[idx]);
        float v = __ldg(&val[idx]);
        const float* xr = x + (size_t)c*DIM;
        #pragma unroll
        for (int u = 0; u < 7; u++) {
            int j = lane + 32*u;
            if (j < 200) acc[u] = fmaf(v, xr[j], acc[u]);
        }
    }
    float* yr = y + (size_t)r*DIM;
    #pragma unroll
    for (int u = 0; u < 7; u++) {
        int j = lane + 32*u;
        if (j < 200) yr[j] = acc[u];
    }
}

// ---------------- mix: y = m*x + (1-m)*mp ----------------------------------
__global__ void mix_k(const float* __restrict__ x, const float* __restrict__ mp,
                      const float* __restrict__ mask, float* __restrict__ y) {
    int idx = blockIdx.x*blockDim.x + threadIdx.x;
    if (idx >= NE*DIM) return;
    float m = mask[idx / DIM];
    y[idx] = m*x[idx] + (1.f - m)*mp[idx];
}

// ---------------- RESCAL: hr[b,j] = sum_k e0[sub[b],k] * R[k,j] ------------
__global__ void rescal_k(const float* __restrict__ e0, const float* __restrict__ rel_emb,
                         const int* __restrict__ sub, const int* __restrict__ rel,
                         float* __restrict__ hr) {
    int b = blockIdx.x;
    int j = threadIdx.x;
    __shared__ float ls[DIM];
    const float* lhs = e0 + (size_t)sub[b]*DIM;
    if (j < DIM) ls[j] = lhs[j];
    __syncthreads();
    if (j < DIM) {
        const float* R = rel_emb + (size_t)rel[b]*RELD;
        float acc = 0.f;
        #pragma unroll 4
        for (int k = 0; k < DIM; k++) acc = fmaf(ls[k], R[(size_t)k*DIM + j], acc);
        hr[(size_t)b*DIM + j] = acc;
    }
}

// ---------------- scores: sigmoid(HR(1024x200) @ E0(50000x200)^T) ----------
// tiles 64x64, K tiled by 40; k-major smem tiles (padded) for conflict-free reads
__global__ void scores_k(const float* __restrict__ HR, const float* __restrict__ E0,
                         float* __restrict__ out) {
    __shared__ float As[40][65];
    __shared__ float Bs[40][65];
    int bx = blockIdx.x;  // n tile
    int by = blockIdx.y;  // m tile
    int tid = threadIdx.x;
    int tx = tid & 15, ty = tid >> 4;
    float acc[4][4];
    #pragma unroll
    for (int i = 0; i < 4; i++)
        #pragma unroll
        for (int p = 0; p < 4; p++) acc[i][p] = 0.f;

    for (int k0 = 0; k0 < 200; k0 += 40) {
        for (int t = tid; t < 64*40; t += 256) {
            int r = t/40, c = t%40;
            As[c][r] = HR[(size_t)(by*64 + r)*DIM + k0 + c];
            int gn = bx*64 + r;
            Bs[c][r] = (gn < NE) ? E0[(size_t)gn*DIM + k0 + c] : 0.f;
        }
        __syncthreads();
        #pragma unroll
        for (int k = 0; k < 40; k++) {
            float a[4], b[4];
            #pragma unroll
            for (int i = 0; i < 4; i++) a[i] = As[k][ty*4+i];
            #pragma unroll
            for (int p = 0; p < 4; p++) b[p] = Bs[k][tx*4+p];
            #pragma unroll
            for (int i = 0; i < 4; i++)
                #pragma unroll
                for (int p = 0; p < 4; p++) acc[i][p] = fmaf(a[i], b[p], acc[i][p]);
        }
        __syncthreads();
    }
    #pragma unroll
    for (int i = 0; i < 4; i++) {
        int m = by*64 + ty*4 + i;
        #pragma unroll
        for (int p = 0; p < 4; p++) {
            int n = bx*64 + tx*4 + p;
            if (n < NE) {
                float v = acc[i][p];
                out[(size_t)m*NE + n] = 1.f/(1.f + expf(-v));
            }
        }
    }
}

// ---------------- launch ---------------------------------------------------
extern "C" void kernel_launch(void* const* d_in, const int* in_sizes, int n_in,
                              void* d_out, int out_size) {
    const float* e0       = (const float*)d_in[0];
    const float* rel_emb  = (const float*)d_in[1];
    const float* nW1      = (const float*)d_in[2];
    const float* nb1      = (const float*)d_in[3];
    const float* nW2      = (const float*)d_in[4];
    const float* nb2      = (const float*)d_in[5];
    const float* eW1      = (const float*)d_in[6];
    const float* eb1      = (const float*)d_in[7];
    const float* eW2      = (const float*)d_in[8];
    const float* eb2      = (const float*)d_in[9];
    const int*   adj_row  = (const int*)d_in[10];
    const int*   adj_col  = (const int*)d_in[11];
    const float* adj_val  = (const float*)d_in[12];
    const int*   rw_row   = (const int*)d_in[13];
    const int*   rw_col   = (const int*)d_in[14];
    const float* rw_val   = (const float*)d_in[15];
    const float* node_eps = (const float*)d_in[16];
    const float* edge_eps = (const float*)d_in[17];
    const int*   sub      = (const int*)d_in[18];
    const int*   rel      = (const int*)d_in[19];

    int E   = in_sizes[10];
    int Erw = in_sizes[13];

    float* out        = (float*)d_out;
    float* out_scores = out;
    float* out_xnd    = out + (size_t)BATCH*NE;
    float* out_xed    = out_xnd + (size_t)NE*DIM;

    float *U, *V, *H, *X1, *X2, *MP, *HR, *NMASK, *NEWEDGE;
    int *RPA, *RPR;
    cudaGetSymbolAddress((void**)&U, g_U);
    cudaGetSymbolAddress((void**)&V, g_V);
    cudaGetSymbolAddress((void**)&H, g_H);
    cudaGetSymbolAddress((void**)&X1, g_X1);
    cudaGetSymbolAddress((void**)&X2, g_X2);
    cudaGetSymbolAddress((void**)&MP, g_MP);
    cudaGetSymbolAddress((void**)&HR, g_HR);
    cudaGetSymbolAddress((void**)&NMASK, g_NMASK);
    cudaGetSymbolAddress((void**)&NEWEDGE, g_NEWEDGE);
    cudaGetSymbolAddress((void**)&RPA, g_rp_adj);
    cudaGetSymbolAddress((void**)&RPR, g_rp_rw);

    const int GB = (NE + 63)/64;                 // 782 row tiles for M=NE
    const int SPB = (NE*32 + 255)/256;           // warp-per-row SpMM blocks
    const int MIXB = (NE*DIM + 255)/256;
    const int NGB = SPB;

    // CSR rowptrs
    rowptr_k<<<(NE+1+255)/256, 256>>>(adj_row, E, RPA);
    rowptr_k<<<(NE+1+255)/256, 256>>>(rw_row, Erw, RPR);

    // node masks i=0,1
    for (int i = 0; i < 2; i++) {
        gemm_k200<<<GB, 256>>>(e0, nW1 + (size_t)i*DIM*DIM, nb1 + i*DIM, H, NE, 1);
        node_gate_k<<<NGB, 256>>>(H, nW2 + i*DIM, nb2 + i, node_eps + (size_t)i*NE,
                                  NMASK + (size_t)i*NE);
    }

    // edge mask i=1: U = e0 @ W1_top ; V = e0 @ W1_bot + b
    const float* eW1_1 = eW1 + (size_t)1*2*DIM*DIM;       // edge_W1[1] (400x200)
    gemm_k200<<<GB, 256>>>(e0, eW1_1,               nullptr,       U, NE, 0);
    gemm_k200<<<GB, 256>>>(e0, eW1_1 + (size_t)DIM*DIM, eb1 + DIM, V, NE, 0);
    edge_gate_k<<<(E*32 + 255)/256, 256>>>(adj_row, adj_col, adj_val,
                                           eW2 + DIM, eb2 + 1, edge_eps + E, NEWEDGE, E);

    // node-drop branch
    spmm_k<<<SPB, 256>>>(RPR, rw_col, rw_val, e0, MP);
    mix_k<<<MIXB, 256>>>(e0, MP, NMASK, X1);
    spmm_k<<<SPB, 256>>>(RPA, adj_col, adj_val, X1, X2);
    spmm_k<<<SPB, 256>>>(RPR, rw_col, rw_val, X2, MP);
    mix_k<<<MIXB, 256>>>(X2, MP, NMASK + NE, X1);
    spmm_k<<<SPB, 256>>>(RPA, adj_col, adj_val, X1, out_xnd);

    // edge-drop branch
    spmm_k<<<SPB, 256>>>(RPR, rw_col, rw_val, e0, X1);
    spmm_k<<<SPB, 256>>>(RPR, rw_col, rw_val, X1, X2);
    spmm_k<<<SPB, 256>>>(RPA, adj_col, NEWEDGE, X2, out_xed);

    // RESCAL + scores
    rescal_k<<<BATCH, 256>>>(e0, rel_emb, sub, rel, HR);
    dim3 sgrid((NE + 63)/64, BATCH/64);
    scores_k<<<sgrid, 256>>>(HR, e0, out_scores);
}

// round 3
// speedup vs baseline: 1.8505x; 1.8505x over previous
#include <cuda_runtime.h>
#include <cuda_bf16.h>
#include <math.h>
#include <stdint.h>

#define NE    50000
#define DIM   200
#define BATCH 1024
#define EMAX  400000
#define RELD  40000
#define KEXT  640          // [hi(200) | lo/hi(200) | hi/lo(200) | zero-pad(40)]
#define NCHUNK 10          // 10 chunks of 64 bf16 cols (128B rows)
#define NPAD  256          // padded N for weight matrices

// ---------------- scratch (device globals; zero-init => pad regions stay 0)
__device__ __align__(16) __nv_bfloat16 g_e0A[(size_t)NE*KEXT];    // e0 as A: [hi, lo, hi]
__device__ __align__(16) __nv_bfloat16 g_e0B[(size_t)NE*KEXT];    // e0 as B: [hi, hi, lo]
__device__ __align__(16) __nv_bfloat16 g_hrA[(size_t)BATCH*KEXT]; // HR as A: [hi, lo, hi]
__device__ __align__(16) __nv_bfloat16 g_WtB[(size_t)4*NPAD*KEXT];// W^T as B: [hi, hi, lo]
__device__ float g_U [NE*DIM];
__device__ float g_V [NE*DIM];
__device__ float g_X1[NE*DIM];
__device__ float g_X2[NE*DIM];
__device__ float g_MP[NE*DIM];
__device__ float g_HR[BATCH*DIM];
__device__ float g_NMASK[2*NE];
__device__ float g_NEWEDGE[EMAX];
__device__ int   g_rp_adj[NE+1];
__device__ int   g_rp_rw [NE+1];

// ================= helpers =================
__device__ __forceinline__ uint32_t smem_u32(const void* p) {
    uint32_t a;
    asm("{ .reg .u64 t; cvta.to.shared.u64 t, %1; cvt.u32.u64 %0, t; }" : "=r"(a) : "l"(p));
    return a;
}
#define SW128(o) ((o) ^ (((o) >> 3) & 0x70))

__device__ __forceinline__ void ldmx4(uint32_t* r, uint32_t addr) {
    asm volatile("ldmatrix.sync.aligned.m8n8.x4.shared.b16 {%0,%1,%2,%3}, [%4];"
        : "=r"(r[0]), "=r"(r[1]), "=r"(r[2]), "=r"(r[3]) : "r"(addr));
}
__device__ __forceinline__ void mma16816(float* c, const uint32_t* a, const uint32_t* b) {
    asm volatile("mma.sync.aligned.m16n8k16.row.col.f32.bf16.bf16.f32 "
        "{%0,%1,%2,%3}, {%4,%5,%6,%7}, {%8,%9}, {%0,%1,%2,%3};"
        : "+f"(c[0]), "+f"(c[1]), "+f"(c[2]), "+f"(c[3])
        : "r"(a[0]), "r"(a[1]), "r"(a[2]), "r"(a[3]), "r"(b[0]), "r"(b[1]));
}

__device__ __forceinline__ float gate_fn(float logits, float u) {
    const float bias = 1e-4f;
    float eps = (2.f*bias - 1.f)*u + (1.f - bias);
    float t = 2.f*(logf(eps) - log1pf(-eps) + logits);
    return 1.f/(1.f + expf(-t));
}
__device__ __forceinline__ float warp_sum(float v) {
    #pragma unroll
    for (int o = 16; o; o >>= 1) v += __shfl_xor_sync(0xffffffffu, v, o);
    return v;
}

// ================= conversion kernels =================
__global__ void conv_e0_k(const float* __restrict__ e0) {
    int t = blockIdx.x*blockDim.x + threadIdx.x;
    if (t >= NE*100) return;
    int row = t/100, k2 = (t%100)*2;
    float2 v = *(const float2*)(e0 + (size_t)row*DIM + k2);
    __nv_bfloat16 hx = __float2bfloat16(v.x), hy = __float2bfloat16(v.y);
    __nv_bfloat16 lx = __float2bfloat16(v.x - __bfloat162float(hx));
    __nv_bfloat16 ly = __float2bfloat16(v.y - __bfloat162float(hy));
    __nv_bfloat162 hi; hi.x = hx; hi.y = hy;
    __nv_bfloat162 lo; lo.x = lx; lo.y = ly;
    size_t b = (size_t)row*KEXT + k2;
    *(__nv_bfloat162*)(g_e0A + b)       = hi;
    *(__nv_bfloat162*)(g_e0A + b + 200) = lo;
    *(__nv_bfloat162*)(g_e0A + b + 400) = hi;
    *(__nv_bfloat162*)(g_e0B + b)       = hi;
    *(__nv_bfloat162*)(g_e0B + b + 200) = hi;
    *(__nv_bfloat162*)(g_e0B + b + 400) = lo;
}

__global__ void conv_hr_k(const float* __restrict__ hr) {
    int t = blockIdx.x*blockDim.x + threadIdx.x;
    if (t >= BATCH*100) return;
    int row = t/100, k2 = (t%100)*2;
    float2 v = *(const float2*)(hr + (size_t)row*DIM + k2);
    __nv_bfloat16 hx = __float2bfloat16(v.x), hy = __float2bfloat16(v.y);
    __nv_bfloat16 lx = __float2bfloat16(v.x - __bfloat162float(hx));
    __nv_bfloat16 ly = __float2bfloat16(v.y - __bfloat162float(hy));
    __nv_bfloat162 hi; hi.x = hx; hi.y = hy;
    __nv_bfloat162 lo; lo.x = lx; lo.y = ly;
    size_t b = (size_t)row*KEXT + k2;
    *(__nv_bfloat162*)(g_hrA + b)       = hi;
    *(__nv_bfloat162*)(g_hrA + b + 200) = lo;
    *(__nv_bfloat162*)(g_hrA + b + 400) = hi;
}

// W (k-major src[k][n]) -> Wt_ext[n][KEXT] (B role [hi,hi,lo]); rows 200..255 stay 0
__global__ void conv_w_k(const float* __restrict__ nW1, const float* __restrict__ eW1) {
    int inst = blockIdx.y;
    int t = blockIdx.x*blockDim.x + threadIdx.x;
    if (t >= DIM*DIM) return;
    const float* src;
    if (inst == 0)      src = nW1;
    else if (inst == 1) src = nW1 + RELD;
    else if (inst == 2) src = eW1 + 2*RELD;   // edge_W1[1] top
    else                src = eW1 + 3*RELD;   // edge_W1[1] bottom
    int n = t/DIM, k = t%DIM;
    float v = src[(size_t)k*DIM + n];
    __nv_bfloat16 hi = __float2bfloat16(v);
    __nv_bfloat16 lo = __float2bfloat16(v - __bfloat162float(hi));
    __nv_bfloat16* dst = g_WtB + (size_t)inst*NPAD*KEXT + (size_t)n*KEXT + k;
    dst[0]   = hi;
    dst[200] = hi;
    dst[400] = lo;
}

// ================= shared HMMA mainloop ====================================
// BM=128, BN=64, BK=64 (one 128B chunk). 8 warps: 4(M) x 2(N), warp tile 32x32.
// acc[mt][nt][4]: mt in {0,1} (m16 tiles), nt in {0..3} (n8 tiles).
struct MmaCtx {
    uint32_t aA, aB;
    int aAtom0, aAtom1, aLine0, aLine1, aKadd;
    int bAtom0, bAtom1, bLine0, bLine1, bKadd;
};

__device__ __forceinline__ void mma_setup(MmaCtx& cx, uint32_t aA, uint32_t aB, int tid) {
    int lane = tid & 31, i = lane >> 3, rr = lane & 7;
    int w = tid >> 5;
    int wm = w >> 1, wn = w & 1;
    int ar0 = wm*32 + (i&1)*8 + rr;        // m-tile 0 row
    int ar1 = ar0 + 16;                    // m-tile 1 row
    int br0 = wn*32 + (i>>1)*8 + rr;       // n-pair 0 row
    int br1 = br0 + 16;                    // n-pair 1 row
    cx.aA = aA; cx.aB = aB;
    cx.aAtom0 = (ar0>>3)*1024; cx.aLine0 = (ar0&7)*128;
    cx.aAtom1 = (ar1>>3)*1024; cx.aLine1 = (ar1&7)*128;
    cx.aKadd = (i>>1)*16;
    cx.bAtom0 = (br0>>3)*1024; cx.bLine0 = (br0&7)*128;
    cx.bAtom1 = (br1>>3)*1024; cx.bLine1 = (br1&7)*128;
    cx.bKadd = (i&1)*16;
}

__device__ __forceinline__ void mma_chunk(const MmaCtx& cx, float acc[2][4][4]) {
    #pragma unroll
    for (int ks = 0; ks < 4; ks++) {
        int kb = ks*32;
        uint32_t a0[4], a1[4], b0[4], b1[4];
        int ia0 = cx.aLine0 + kb + cx.aKadd;
        int ia1 = cx.aLine1 + kb + cx.aKadd;
        int ib0 = cx.bLine0 + kb + cx.bKadd;
        int ib1 = cx.bLine1 + kb + cx.bKadd;
        ldmx4(a0, cx.aA + cx.aAtom0 + SW128(ia0));
        ldmx4(a1, cx.aA + cx.aAtom1 + SW128(ia1));
        ldmx4(b0, cx.aB + cx.bAtom0 + SW128(ib0));
        ldmx4(b1, cx.aB + cx.bAtom1 + SW128(ib1));
        mma16816(acc[0][0], a0, b0);
        mma16816(acc[0][1], a0, b0 + 2);
        mma16816(acc[0][2], a0, b1);
        mma16816(acc[0][3], a0, b1 + 2);
        mma16816(acc[1][0], a1, b0);
        mma16816(acc[1][1], a1, b0 + 2);
        mma16816(acc[1][2], a1, b1);
        mma16816(acc[1][3], a1, b1 + 2);
    }
}

// chunk loaders (SW128 atom layout: off = (r>>3)*1024 + SW128((r&7)*128 + q*16))
__device__ __forceinline__ void load_a128(uint8_t* sA, const __nv_bfloat16* Ag,
                                          int row0, int rmax, int c, int tid) {
    #pragma unroll
    for (int i = 0; i < 4; i++) {
        int idx = tid + i*256;
        int r = idx >> 3, q = idx & 7;
        int gr = row0 + r; if (gr >= rmax) gr = 0;
        uint4 v = *(const uint4*)(Ag + (size_t)gr*KEXT + c*64 + q*8);
        uint32_t off = (uint32_t)((r>>3)*1024) + SW128((uint32_t)((r&7)*128 + q*16));
        *(uint4*)(sA + off) = v;
    }
}
__device__ __forceinline__ void load_b64(uint8_t* sB, const __nv_bfloat16* Bg,
                                         int row0, int rmax, int c, int tid) {
    #pragma unroll
    for (int i = 0; i < 2; i++) {
        int idx = tid + i*256;
        int r = idx >> 3, q = idx & 7;
        int gr = row0 + r; if (gr >= rmax) gr = 0;
        uint4 v = *(const uint4*)(Bg + (size_t)gr*KEXT + c*64 + q*8);
        uint32_t off = (uint32_t)((r>>3)*1024) + SW128((uint32_t)((r&7)*128 + q*16));
        *(uint4*)(sB + off) = v;
    }
}

// ================= GEMM 1: C[50000 x 200] = e0 @ W (4 instances) ===========
// inst 0 -> H0 (g_X1), inst 1 -> H1 (g_X2) [relu+bias], inst 2 -> U, inst 3 -> V(+bias)
__global__ void __launch_bounds__(256) mm_e0w_k(
    const float* __restrict__ nb1, const float* __restrict__ eb1,
    float* __restrict__ H0, float* __restrict__ H1,
    float* __restrict__ Uo, float* __restrict__ Vo)
{
    __shared__ __align__(1024) uint8_t sA[16384];
    __shared__ __align__(1024) uint8_t sB[8192];
    int bm = blockIdx.x, nt64 = blockIdx.y, inst = blockIdx.z;
    int tid = threadIdx.x;

    MmaCtx cx;
    mma_setup(cx, smem_u32(sA), smem_u32(sB), tid);
    float acc[2][4][4];
    #pragma unroll
    for (int a = 0; a < 2; a++)
        #pragma unroll
        for (int b = 0; b < 4; b++)
            #pragma unroll
            for (int q = 0; q < 4; q++) acc[a][b][q] = 0.f;

    const __nv_bfloat16* Bg = g_WtB + (size_t)inst*NPAD*KEXT;
    for (int c = 0; c < NCHUNK; c++) {
        load_a128(sA, g_e0A, bm*128, NE, c, tid);
        load_b64 (sB, Bg, nt64*64, NPAD, c, tid);
        __syncthreads();
        mma_chunk(cx, acc);
        __syncthreads();
    }

    // epilogue
    int lane = tid & 31, w = tid >> 5;
    int wm = w >> 1, wn = w & 1;
    int mrow = lane >> 2, ncol = (lane & 3)*2;
    float* C; const float* bias; int relu = 0;
    if (inst == 0)      { C = H0; bias = nb1;        relu = 1; }
    else if (inst == 1) { C = H1; bias = nb1 + DIM;  relu = 1; }
    else if (inst == 2) { C = Uo; bias = nullptr; }
    else                { C = Vo; bias = eb1 + DIM; }

    #pragma unroll
    for (int mt = 0; mt < 2; mt++) {
        int m = bm*128 + wm*32 + mt*16 + mrow;
        if (m >= NE) continue;
        #pragma unroll
        for (int nt = 0; nt < 4; nt++) {
            int n = nt64*64 + wn*32 + nt*8 + ncol;
            if (n >= DIM) continue;
            float b0 = bias ? bias[n] : 0.f, b1 = bias ? bias[n+1] : 0.f;
            float2 v01, v23;
            v01.x = acc[mt][nt][0] + b0; v01.y = acc[mt][nt][1] + b1;
            v23.x = acc[mt][nt][2] + b0; v23.y = acc[mt][nt][3] + b1;
            if (relu) {
                v01.x = fmaxf(v01.x, 0.f); v01.y = fmaxf(v01.y, 0.f);
                v23.x = fmaxf(v23.x, 0.f); v23.y = fmaxf(v23.y, 0.f);
            }
            *(float2*)(C + (size_t)m*DIM + n) = v01;
            if (m + 8 < NE) *(float2*)(C + (size_t)(m+8)*DIM + n) = v23;
        }
    }
}

// ================= GEMM 2: scores = sigmoid(HR @ E0^T) =====================
__global__ void __launch_bounds__(256) scores_mm_k(float* __restrict__ out)
{
    __shared__ __align__(1024) uint8_t sA[16384];
    __shared__ __align__(1024) uint8_t sB[8192];
    int bx = blockIdx.x, by = blockIdx.y;
    int tid = threadIdx.x;

    MmaCtx cx;
    mma_setup(cx, smem_u32(sA), smem_u32(sB), tid);
    float acc[2][4][4];
    #pragma unroll
    for (int a = 0; a < 2; a++)
        #pragma unroll
        for (int b = 0; b < 4; b++)
            #pragma unroll
            for (int q = 0; q < 4; q++) acc[a][b][q] = 0.f;

    for (int c = 0; c < NCHUNK; c++) {
        load_a128(sA, g_hrA, by*128, BATCH, c, tid);
        load_b64 (sB, g_e0B, bx*64, NE, c, tid);
        __syncthreads();
        mma_chunk(cx, acc);
        __syncthreads();
    }

    int lane = tid & 31, w = tid >> 5;
    int wm = w >> 1, wn = w & 1;
    int mrow = lane >> 2, ncol = (lane & 3)*2;
    #pragma unroll
    for (int mt = 0; mt < 2; mt++) {
        int m = by*128 + wm*32 + mt*16 + mrow;  // < 1024 always
        #pragma unroll
        for (int nt = 0; nt < 4; nt++) {
            int n = bx*64 + wn*32 + nt*8 + ncol;
            if (n < NE) {
                float2 v01, v23;
                v01.x = 1.f/(1.f + __expf(-acc[mt][nt][0]));
                v01.y = 1.f/(1.f + __expf(-acc[mt][nt][1]));
                v23.x = 1.f/(1.f + __expf(-acc[mt][nt][2]));
                v23.y = 1.f/(1.f + __expf(-acc[mt][nt][3]));
                *(float2*)(out + (size_t)m*NE + n) = v01;
                *(float2*)(out + (size_t)(m+8)*NE + n) = v23;
            }
        }
    }
}

// ================= support kernels (R1, passing) =================
__global__ void rowptr_k(const int* __restrict__ row, int nnz, int* __restrict__ rowptr) {
    int n = blockIdx.x*blockDim.x + threadIdx.x;
    if (n > NE) return;
    int lo = 0, hi = nnz;
    while (lo < hi) { int mid = (lo+hi) >> 1; if (row[mid] < n) lo = mid+1; else hi = mid; }
    rowptr[n] = lo;
}

__global__ void node_gate_k(const float* __restrict__ H, const float* __restrict__ W2,
                            const float* __restrict__ b2, const float* __restrict__ eps,
                            float* __restrict__ mask) {
    int w = (blockIdx.x*blockDim.x + threadIdx.x) >> 5;
    int lane = threadIdx.x & 31;
    if (w >= NE) return;
    float acc = 0.f;
    const float* hr = H + (size_t)w*DIM;
    #pragma unroll
    for (int u = 0; u < 7; u++) {
        int j = lane + 32*u;
        if (j < 200) acc = fmaf(hr[j], W2[j], acc);
    }
    acc = warp_sum(acc);
    if (lane == 0) mask[w] = gate_fn(acc + b2[0], eps[w]);
}

__global__ void edge_gate_k(const int* __restrict__ row, const int* __restrict__ col,
                            const float* __restrict__ adj_val,
                            const float* __restrict__ W2, const float* __restrict__ b2,
                            const float* __restrict__ eps, float* __restrict__ new_edge,
                            int E) {
    int e = (blockIdx.x*blockDim.x + threadIdx.x) >> 5;
    int lane = threadIdx.x & 31;
    if (e >= E) return;
    int r = row[e], c = col[e];
    const float* ur = g_U + (size_t)r*DIM;
    const float* vr = g_V + (size_t)c*DIM;
    float acc = 0.f;
    #pragma unroll
    for (int u = 0; u < 7; u++) {
        int j = lane + 32*u;
        if (j < 200) {
            float he = fmaxf(ur[j] + vr[j], 0.f);
            acc = fmaf(he, W2[j], acc);
        }
    }
    acc = warp_sum(acc);
    if (lane == 0) new_edge[e] = adj_val[e] * gate_fn(acc + b2[0], eps[e]);
}

__global__ void spmm_k(const int* __restrict__ rowptr, const int* __restrict__ col,
                       const float* __restrict__ val, const float* __restrict__ x,
                       float* __restrict__ y) {
    int r = (blockIdx.x*blockDim.x + threadIdx.x) >> 5;
    int lane = threadIdx.x & 31;
    if (r >= NE) return;
    float acc[7];
    #pragma unroll
    for (int u = 0; u < 7; u++) acc[u] = 0.f;
    int s = rowptr[r], e = rowptr[r+1];
    for (int idx = s; idx < e; idx++) {
        int c = __ldg(&col[idx]);
        float v = __ldg(&val[idx]);
        const float* xr = x + (size_t)c*DIM;
        #pragma unroll
        for (int u = 0; u < 7; u++) {
            int j = lane + 32*u;
            if (j < 200) acc[u] = fmaf(v, xr[j], acc[u]);
        }
    }
    float* yr = y + (size_t)r*DIM;
    #pragma unroll
    for (int u = 0; u < 7; u++) {
        int j = lane + 32*u;
        if (j < 200) yr[j] = acc[u];
    }
}

__global__ void mix_k(const float* __restrict__ x, const float* __restrict__ mp,
                      const float* __restrict__ mask, float* __restrict__ y) {
    int idx = blockIdx.x*blockDim.x + threadIdx.x;
    if (idx >= NE*DIM) return;
    float m = mask[idx / DIM];
    y[idx] = m*x[idx] + (1.f - m)*mp[idx];
}

__global__ void rescal_k(const float* __restrict__ e0, const float* __restrict__ rel_emb,
                         const int* __restrict__ sub, const int* __restrict__ rel,
                         float* __restrict__ hr) {
    int b = blockIdx.x;
    int j = threadIdx.x;
    __shared__ float ls[DIM];
    const float* lhs = e0 + (size_t)sub[b]*DIM;
    if (j < DIM) ls[j] = lhs[j];
    __syncthreads();
    if (j < DIM) {
        const float* R = rel_emb + (size_t)rel[b]*RELD;
        float acc = 0.f;
        #pragma unroll 4
        for (int k = 0; k < DIM; k++) acc = fmaf(ls[k], R[(size_t)k*DIM + j], acc);
        hr[(size_t)b*DIM + j] = acc;
    }
}

// ================= launch ==================================================
extern "C" void kernel_launch(void* const* d_in, const int* in_sizes, int n_in,
                              void* d_out, int out_size) {
    const float* e0       = (const float*)d_in[0];
    const float* rel_emb  = (const float*)d_in[1];
    const float* nW1      = (const float*)d_in[2];
    const float* nb1      = (const float*)d_in[3];
    const float* nW2      = (const float*)d_in[4];
    const float* nb2      = (const float*)d_in[5];
    const float* eW1      = (const float*)d_in[6];
    const float* eb1      = (const float*)d_in[7];
    const float* eW2      = (const float*)d_in[8];
    const float* eb2      = (const float*)d_in[9];
    const int*   adj_row  = (const int*)d_in[10];
    const int*   adj_col  = (const int*)d_in[11];
    const float* adj_val  = (const float*)d_in[12];
    const int*   rw_row   = (const int*)d_in[13];
    const int*   rw_col   = (const int*)d_in[14];
    const float* rw_val   = (const float*)d_in[15];
    const float* node_eps = (const float*)d_in[16];
    const float* edge_eps = (const float*)d_in[17];
    const int*   sub      = (const int*)d_in[18];
    const int*   rel      = (const int*)d_in[19];

    int E   = in_sizes[10];
    int Erw = in_sizes[13];

    float* out        = (float*)d_out;
    float* out_scores = out;
    float* out_xnd    = out + (size_t)BATCH*NE;
    float* out_xed    = out_xnd + (size_t)NE*DIM;

    float *U, *V, *X1, *X2, *MP, *HR, *NMASK, *NEWEDGE;
    int *RPA, *RPR;
    cudaGetSymbolAddress((void**)&U, g_U);
    cudaGetSymbolAddress((void**)&V, g_V);
    cudaGetSymbolAddress((void**)&X1, g_X1);
    cudaGetSymbolAddress((void**)&X2, g_X2);
    cudaGetSymbolAddress((void**)&MP, g_MP);
    cudaGetSymbolAddress((void**)&HR, g_HR);
    cudaGetSymbolAddress((void**)&NMASK, g_NMASK);
    cudaGetSymbolAddress((void**)&NEWEDGE, g_NEWEDGE);
    cudaGetSymbolAddress((void**)&RPA, g_rp_adj);
    cudaGetSymbolAddress((void**)&RPR, g_rp_rw);

    const int SPB  = (NE*32 + 255)/256;
    const int MIXB = (NE*DIM + 255)/256;
    const int MT   = (NE + 127)/128;      // 391

    // rowptrs + conversions
    rowptr_k<<<(NE+1+255)/256, 256>>>(adj_row, E, RPA);
    rowptr_k<<<(NE+1+255)/256, 256>>>(rw_row, Erw, RPR);
    conv_e0_k<<<(NE*100 + 255)/256, 256>>>(e0);
    dim3 wgrid((DIM*DIM + 255)/256, 4);
    conv_w_k<<<wgrid, 256>>>(nW1, eW1);

    // HMMA GEMM: H0 (X1), H1 (X2), U, V
    dim3 mgrid(MT, 4, 4);
    mm_e0w_k<<<mgrid, 256>>>(nb1, eb1, X1, X2, U, V);

    // gates
    node_gate_k<<<SPB, 256>>>(X1, nW2,       nb2,     node_eps,      NMASK);
    node_gate_k<<<SPB, 256>>>(X2, nW2 + DIM, nb2 + 1, node_eps + NE, NMASK + NE);
    edge_gate_k<<<(E*32 + 255)/256, 256>>>(adj_row, adj_col, adj_val,
                                           eW2 + DIM, eb2 + 1, edge_eps + E, NEWEDGE, E);

    // node-drop branch
    spmm_k<<<SPB, 256>>>(RPR, rw_col, rw_val, e0, MP);
    mix_k<<<MIXB, 256>>>(e0, MP, NMASK, X1);
    spmm_k<<<SPB, 256>>>(RPA, adj_col, adj_val, X1, X2);
    spmm_k<<<SPB, 256>>>(RPR, rw_col, rw_val, X2, MP);
    mix_k<<<MIXB, 256>>>(X2, MP, NMASK + NE, X1);
    spmm_k<<<SPB, 256>>>(RPA, adj_col, adj_val, X1, out_xnd);

    // edge-drop branch
    spmm_k<<<SPB, 256>>>(RPR, rw_col, rw_val, e0, X1);
    spmm_k<<<SPB, 256>>>(RPR, rw_col, rw_val, X1, X2);
    spmm_k<<<SPB, 256>>>(RPA, adj_col, NEWEDGE, X2, out_xed);

    // RESCAL + scores
    rescal_k<<<BATCH, 256>>>(e0, rel_emb, sub, rel, HR);
    conv_hr_k<<<(BATCH*100 + 255)/256, 256>>>(HR);
    dim3 sgrid((NE + 63)/64, BATCH/128);
    scores_mm_k<<<sgrid, 256>>>(out_scores);
}

// round 4
// speedup vs baseline: 3.4341x; 1.8557x over previous
#include <cuda_runtime.h>
#include <cuda_bf16.h>
#include <math.h>
#include <stdint.h>

#define NE    50000
#define DIM   200
#define BATCH 1024
#define EMAX  400000
#define RELD  40000
#define KPAD  256          // [data(200) | zero-pad(56)]
#define NCHUNK 4           // 4 chunks of 64 bf16 cols (128B rows)
#define NPAD  256          // padded N for weight matrices

// ---------------- scratch (device globals; zero-init => pad regions stay 0)
__device__ __align__(16) __nv_bfloat16 g_e0b[(size_t)NE*KPAD];    // e0 bf16
__device__ __align__(16) __nv_bfloat16 g_hrb[(size_t)BATCH*KPAD]; // HR bf16
__device__ __align__(16) __nv_bfloat16 g_Wtb[(size_t)4*NPAD*KPAD];// W^T bf16
__device__ float g_U [NE*DIM];
__device__ float g_V [NE*DIM];
__device__ float g_X1[NE*DIM];
__device__ float g_X2[NE*DIM];
__device__ float g_MP[NE*DIM];
__device__ float g_HR[BATCH*DIM];
__device__ float g_NMASK[2*NE];
__device__ float g_NEWEDGE[EMAX];
__device__ int   g_rp_adj[NE+1];
__device__ int   g_rp_rw [NE+1];

// ================= helpers =================
__device__ __forceinline__ uint32_t smem_u32(const void* p) {
    uint32_t a;
    asm("{ .reg .u64 t; cvta.to.shared.u64 t, %1; cvt.u32.u64 %0, t; }" : "=r"(a) : "l"(p));
    return a;
}
#define SW128(o) ((o) ^ (((o) >> 3) & 0x70))

__device__ __forceinline__ void ldmx4(uint32_t* r, uint32_t addr) {
    asm volatile("ldmatrix.sync.aligned.m8n8.x4.shared.b16 {%0,%1,%2,%3}, [%4];"
        : "=r"(r[0]), "=r"(r[1]), "=r"(r[2]), "=r"(r[3]) : "r"(addr));
}
__device__ __forceinline__ void mma16816(float* c, const uint32_t* a, const uint32_t* b) {
    asm volatile("mma.sync.aligned.m16n8k16.row.col.f32.bf16.bf16.f32 "
        "{%0,%1,%2,%3}, {%4,%5,%6,%7}, {%8,%9}, {%0,%1,%2,%3};"
        : "+f"(c[0]), "+f"(c[1]), "+f"(c[2]), "+f"(c[3])
        : "r"(a[0]), "r"(a[1]), "r"(a[2]), "r"(a[3]), "r"(b[0]), "r"(b[1]));
}
__device__ __forceinline__ void cpa16(uint32_t dst, const void* src) {
    asm volatile("cp.async.cg.shared.global [%0], [%1], 16;" :: "r"(dst), "l"(src));
}
#define CPA_COMMIT() asm volatile("cp.async.commit_group;" ::: "memory")
#define CPA_WAIT(n)  asm volatile("cp.async.wait_group %0;" :: "n"(n) : "memory")

__device__ __forceinline__ float gate_fn(float logits, float u) {
    const float bias = 1e-4f;
    float eps = (2.f*bias - 1.f)*u + (1.f - bias);
    float t = 2.f*(logf(eps) - log1pf(-eps) + logits);
    return 1.f/(1.f + expf(-t));
}
__device__ __forceinline__ float warp_sum(float v) {
    #pragma unroll
    for (int o = 16; o; o >>= 1) v += __shfl_xor_sync(0xffffffffu, v, o);
    return v;
}

// ================= conversion kernels =================
__global__ void conv_e0_k(const float* __restrict__ e0) {
    int t = blockIdx.x*blockDim.x + threadIdx.x;
    if (t >= NE*50) return;
    int row = t/50, k = (t%50)*4;
    float4 v = *(const float4*)(e0 + (size_t)row*DIM + k);
    __nv_bfloat162 p0, p1;
    p0.x = __float2bfloat16(v.x); p0.y = __float2bfloat16(v.y);
    p1.x = __float2bfloat16(v.z); p1.y = __float2bfloat16(v.w);
    __nv_bfloat16* d = g_e0b + (size_t)row*KPAD + k;
    *(__nv_bfloat162*)(d)     = p0;
    *(__nv_bfloat162*)(d + 2) = p1;
}

__global__ void conv_hr_k(const float* __restrict__ hr) {
    int t = blockIdx.x*blockDim.x + threadIdx.x;
    if (t >= BATCH*50) return;
    int row = t/50, k = (t%50)*4;
    float4 v = *(const float4*)(hr + (size_t)row*DIM + k);
    __nv_bfloat162 p0, p1;
    p0.x = __float2bfloat16(v.x); p0.y = __float2bfloat16(v.y);
    p1.x = __float2bfloat16(v.z); p1.y = __float2bfloat16(v.w);
    __nv_bfloat16* d = g_hrb + (size_t)row*KPAD + k;
    *(__nv_bfloat162*)(d)     = p0;
    *(__nv_bfloat162*)(d + 2) = p1;
}

// W (k-major src[k][n]) -> Wt[n][KPAD]; rows 200..255 and cols 200..255 stay 0
__global__ void conv_w_k(const float* __restrict__ nW1, const float* __restrict__ eW1) {
    int inst = blockIdx.y;
    int t = blockIdx.x*blockDim.x + threadIdx.x;
    if (t >= DIM*DIM) return;
    const float* src;
    if (inst == 0)      src = nW1;
    else if (inst == 1) src = nW1 + RELD;
    else if (inst == 2) src = eW1 + 2*RELD;   // edge_W1[1] top
    else                src = eW1 + 3*RELD;   // edge_W1[1] bottom
    int n = t/DIM, k = t%DIM;
    g_Wtb[(size_t)inst*NPAD*KPAD + (size_t)n*KPAD + k] = __float2bfloat16(src[(size_t)k*DIM + n]);
}

// ================= shared HMMA machinery ===================================
// BM=128, BN=64, BK=64. 8 warps: 4(M) x 2(N), warp tile 32x32.
struct MmaCtx {
    int aAtom0, aAtom1, aLine0, aLine1, aKadd;
    int bAtom0, bAtom1, bLine0, bLine1, bKadd;
};

__device__ __forceinline__ void mma_setup(MmaCtx& cx, int tid) {
    int lane = tid & 31, i = lane >> 3, rr = lane & 7;
    int w = tid >> 5;
    int wm = w >> 1, wn = w & 1;
    int ar0 = wm*32 + (i&1)*8 + rr;
    int ar1 = ar0 + 16;
    int br0 = wn*32 + (i>>1)*8 + rr;
    int br1 = br0 + 16;
    cx.aAtom0 = (ar0>>3)*1024; cx.aLine0 = (ar0&7)*128;
    cx.aAtom1 = (ar1>>3)*1024; cx.aLine1 = (ar1&7)*128;
    cx.aKadd = (i>>1)*16;
    cx.bAtom0 = (br0>>3)*1024; cx.bLine0 = (br0&7)*128;
    cx.bAtom1 = (br1>>3)*1024; cx.bLine1 = (br1&7)*128;
    cx.bKadd = (i&1)*16;
}

__device__ __forceinline__ void mma_chunk(const MmaCtx& cx, uint32_t aA, uint32_t aB,
                                          float acc[2][4][4]) {
    #pragma unroll
    for (int ks = 0; ks < 4; ks++) {
        int kb = ks*32;
        uint32_t a0[4], a1[4], b0[4], b1[4];
        ldmx4(a0, aA + cx.aAtom0 + SW128(cx.aLine0 + kb + cx.aKadd));
        ldmx4(a1, aA + cx.aAtom1 + SW128(cx.aLine1 + kb + cx.aKadd));
        ldmx4(b0, aB + cx.bAtom0 + SW128(cx.bLine0 + kb + cx.bKadd));
        ldmx4(b1, aB + cx.bAtom1 + SW128(cx.bLine1 + kb + cx.bKadd));
        mma16816(acc[0][0], a0, b0);
        mma16816(acc[0][1], a0, b0 + 2);
        mma16816(acc[0][2], a0, b1);
        mma16816(acc[0][3], a0, b1 + 2);
        mma16816(acc[1][0], a1, b0);
        mma16816(acc[1][1], a1, b0 + 2);
        mma16816(acc[1][2], a1, b1);
        mma16816(acc[1][3], a1, b1 + 2);
    }
}

// async chunk loaders into SW128 atom layout
__device__ __forceinline__ void load_a128_async(uint32_t sA, const __nv_bfloat16* Ag,
                                                int row0, int rmax, int c, int tid) {
    #pragma unroll
    for (int i = 0; i < 4; i++) {
        int idx = tid + i*256;
        int r = idx >> 3, q = idx & 7;
        int gr = row0 + r; if (gr >= rmax) gr = 0;
        uint32_t off = (uint32_t)((r>>3)*1024) + SW128((uint32_t)((r&7)*128 + q*16));
        cpa16(sA + off, Ag + (size_t)gr*KPAD + c*64 + q*8);
    }
}
__device__ __forceinline__ void load_b64_async(uint32_t sB, const __nv_bfloat16* Bg,
                                               int row0, int rmax, int c, int tid) {
    #pragma unroll
    for (int i = 0; i < 2; i++) {
        int idx = tid + i*256;
        int r = idx >> 3, q = idx & 7;
        int gr = row0 + r; if (gr >= rmax) gr = 0;
        uint32_t off = (uint32_t)((r>>3)*1024) + SW128((uint32_t)((r&7)*128 + q*16));
        cpa16(sB + off, Bg + (size_t)gr*KPAD + c*64 + q*8);
    }
}

// ================= GEMM 1: C[50000 x 200] = e0 @ W (4 instances) ===========
__global__ void __launch_bounds__(256) mm_e0w_k(
    const float* __restrict__ nb1, const float* __restrict__ eb1,
    float* __restrict__ H0, float* __restrict__ H1,
    float* __restrict__ Uo, float* __restrict__ Vo)
{
    __shared__ __align__(1024) uint8_t sA[2][16384];
    __shared__ __align__(1024) uint8_t sB[2][8192];
    int bm = blockIdx.x, nt64 = blockIdx.y, inst = blockIdx.z;
    int tid = threadIdx.x;
    uint32_t aA0 = smem_u32(sA[0]), aA1 = smem_u32(sA[1]);
    uint32_t aB0 = smem_u32(sB[0]), aB1 = smem_u32(sB[1]);

    MmaCtx cx; mma_setup(cx, tid);
    float acc[2][4][4];
    #pragma unroll
    for (int a = 0; a < 2; a++)
        #pragma unroll
        for (int b = 0; b < 4; b++)
            #pragma unroll
            for (int q = 0; q < 4; q++) acc[a][b][q] = 0.f;

    const __nv_bfloat16* Bg = g_Wtb + (size_t)inst*NPAD*KPAD;

    load_a128_async(aA0, g_e0b, bm*128, NE, 0, tid);
    load_b64_async (aB0, Bg, nt64*64, NPAD, 0, tid);
    CPA_COMMIT();
    #pragma unroll
    for (int c = 0; c < NCHUNK; c++) {
        uint32_t curA = (c & 1) ? aA1 : aA0, curB = (c & 1) ? aB1 : aB0;
        if (c + 1 < NCHUNK) {
            uint32_t nxtA = ((c+1) & 1) ? aA1 : aA0, nxtB = ((c+1) & 1) ? aB1 : aB0;
            load_a128_async(nxtA, g_e0b, bm*128, NE, c+1, tid);
            load_b64_async (nxtB, Bg, nt64*64, NPAD, c+1, tid);
            CPA_COMMIT();
            CPA_WAIT(1);
        } else {
            CPA_WAIT(0);
        }
        __syncthreads();
        mma_chunk(cx, curA, curB, acc);
        __syncthreads();
    }

    int lane = tid & 31, w = tid >> 5;
    int wm = w >> 1, wn = w & 1;
    int mrow = lane >> 2, ncol = (lane & 3)*2;
    float* C; const float* bias; int relu = 0;
    if (inst == 0)      { C = H0; bias = nb1;        relu = 1; }
    else if (inst == 1) { C = H1; bias = nb1 + DIM;  relu = 1; }
    else if (inst == 2) { C = Uo; bias = nullptr; }
    else                { C = Vo; bias = eb1 + DIM; }

    #pragma unroll
    for (int mt = 0; mt < 2; mt++) {
        int m = bm*128 + wm*32 + mt*16 + mrow;
        if (m >= NE) continue;
        #pragma unroll
        for (int nt = 0; nt < 4; nt++) {
            int n = nt64*64 + wn*32 + nt*8 + ncol;
            if (n >= DIM) continue;
            float b0 = bias ? bias[n] : 0.f, b1 = bias ? bias[n+1] : 0.f;
            float2 v01, v23;
            v01.x = acc[mt][nt][0] + b0; v01.y = acc[mt][nt][1] + b1;
            v23.x = acc[mt][nt][2] + b0; v23.y = acc[mt][nt][3] + b1;
            if (relu) {
                v01.x = fmaxf(v01.x, 0.f); v01.y = fmaxf(v01.y, 0.f);
                v23.x = fmaxf(v23.x, 0.f); v23.y = fmaxf(v23.y, 0.f);
            }
            *(float2*)(C + (size_t)m*DIM + n) = v01;
            if (m + 8 < NE) *(float2*)(C + (size_t)(m+8)*DIM + n) = v23;
        }
    }
}

// ================= GEMM 2: scores = sigmoid(HR @ E0^T) =====================
__global__ void __launch_bounds__(256) scores_mm_k(float* __restrict__ out)
{
    __shared__ __align__(1024) uint8_t sA[2][16384];
    __shared__ __align__(1024) uint8_t sB[2][8192];
    int bx = blockIdx.x, by = blockIdx.y;
    int tid = threadIdx.x;
    uint32_t aA0 = smem_u32(sA[0]), aA1 = smem_u32(sA[1]);
    uint32_t aB0 = smem_u32(sB[0]), aB1 = smem_u32(sB[1]);

    MmaCtx cx; mma_setup(cx, tid);
    float acc[2][4][4];
    #pragma unroll
    for (int a = 0; a < 2; a++)
        #pragma unroll
        for (int b = 0; b < 4; b++)
            #pragma unroll
            for (int q = 0; q < 4; q++) acc[a][b][q] = 0.f;

    load_a128_async(aA0, g_hrb, by*128, BATCH, 0, tid);
    load_b64_async (aB0, g_e0b, bx*64, NE, 0, tid);
    CPA_COMMIT();
    #pragma unroll
    for (int c = 0; c < NCHUNK; c++) {
        uint32_t curA = (c & 1) ? aA1 : aA0, curB = (c & 1) ? aB1 : aB0;
        if (c + 1 < NCHUNK) {
            uint32_t nxtA = ((c+1) & 1) ? aA1 : aA0, nxtB = ((c+1) & 1) ? aB1 : aB0;
            load_a128_async(nxtA, g_hrb, by*128, BATCH, c+1, tid);
            load_b64_async (nxtB, g_e0b, bx*64, NE, c+1, tid);
            CPA_COMMIT();
            CPA_WAIT(1);
        } else {
            CPA_WAIT(0);
        }
        __syncthreads();
        mma_chunk(cx, curA, curB, acc);
        __syncthreads();
    }

    int lane = tid & 31, w = tid >> 5;
    int wm = w >> 1, wn = w & 1;
    int mrow = lane >> 2, ncol = (lane & 3)*2;
    #pragma unroll
    for (int mt = 0; mt < 2; mt++) {
        int m = by*128 + wm*32 + mt*16 + mrow;
        #pragma unroll
        for (int nt = 0; nt < 4; nt++) {
            int n = bx*64 + wn*32 + nt*8 + ncol;
            if (n < NE) {
                float2 v01, v23;
                v01.x = 1.f/(1.f + __expf(-acc[mt][nt][0]));
                v01.y = 1.f/(1.f + __expf(-acc[mt][nt][1]));
                v23.x = 1.f/(1.f + __expf(-acc[mt][nt][2]));
                v23.y = 1.f/(1.f + __expf(-acc[mt][nt][3]));
                *(float2*)(out + (size_t)m*NE + n) = v01;
                *(float2*)(out + (size_t)(m+8)*NE + n) = v23;
            }
        }
    }
}

// ================= support kernels =================
__global__ void rowptr_k(const int* __restrict__ row, int nnz, int* __restrict__ rowptr) {
    int n = blockIdx.x*blockDim.x + threadIdx.x;
    if (n > NE) return;
    int lo = 0, hi = nnz;
    while (lo < hi) { int mid = (lo+hi) >> 1; if (row[mid] < n) lo = mid+1; else hi = mid; }
    rowptr[n] = lo;
}

__global__ void node_gate_k(const float* __restrict__ H, const float* __restrict__ W2,
                            const float* __restrict__ b2, const float* __restrict__ eps,
                            float* __restrict__ mask) {
    int w = (blockIdx.x*blockDim.x + threadIdx.x) >> 5;
    int lane = threadIdx.x & 31;
    if (w >= NE) return;
    float acc = 0.f;
    const float* hr = H + (size_t)w*DIM;
    #pragma unroll
    for (int u = 0; u < 7; u++) {
        int j = lane + 32*u;
        if (j < 200) acc = fmaf(hr[j], W2[j], acc);
    }
    acc = warp_sum(acc);
    if (lane == 0) mask[w] = gate_fn(acc + b2[0], eps[w]);
}

__global__ void edge_gate_k(const int* __restrict__ row, const int* __restrict__ col,
                            const float* __restrict__ adj_val,
                            const float* __restrict__ W2, const float* __restrict__ b2,
                            const float* __restrict__ eps, float* __restrict__ new_edge,
                            int E) {
    int e = (blockIdx.x*blockDim.x + threadIdx.x) >> 5;
    int lane = threadIdx.x & 31;
    if (e >= E) return;
    int r = row[e], c = col[e];
    const float* ur = g_U + (size_t)r*DIM;
    const float* vr = g_V + (size_t)c*DIM;
    float acc = 0.f;
    #pragma unroll
    for (int u = 0; u < 7; u++) {
        int j = lane + 32*u;
        if (j < 200) {
            float he = fmaxf(ur[j] + vr[j], 0.f);
            acc = fmaf(he, W2[j], acc);
        }
    }
    acc = warp_sum(acc);
    if (lane == 0) new_edge[e] = adj_val[e] * gate_fn(acc + b2[0], eps[e]);
}

// plain CSR SpMM
__global__ void spmm_k(const int* __restrict__ rowptr, const int* __restrict__ col,
                       const float* __restrict__ val, const float* __restrict__ x,
                       float* __restrict__ y) {
    int r = (blockIdx.x*blockDim.x + threadIdx.x) >> 5;
    int lane = threadIdx.x & 31;
    if (r >= NE) return;
    float acc[7];
    #pragma unroll
    for (int u = 0; u < 7; u++) acc[u] = 0.f;
    int s = rowptr[r], e = rowptr[r+1];
    for (int idx = s; idx < e; idx++) {
        int c = __ldg(&col[idx]);
        float v = __ldg(&val[idx]);
        const float* xr = x + (size_t)c*DIM;
        #pragma unroll
        for (int u = 0; u < 7; u++) {
            int j = lane + 32*u;
            if (j < 200) acc[u] = fmaf(v, xr[j], acc[u]);
        }
    }
    float* yr = y + (size_t)r*DIM;
    #pragma unroll
    for (int u = 0; u < 7; u++) {
        int j = lane + 32*u;
        if (j < 200) yr[j] = acc[u];
    }
}

// SpMM + mix fused: mp = spmm row; y = m*x + (1-m)*mp; optionally also write mp
template<int WRITE_MP>
__global__ void spmm_mix_k(const int* __restrict__ rowptr, const int* __restrict__ col,
                           const float* __restrict__ val, const float* __restrict__ x,
                           const float* __restrict__ mask,
                           float* __restrict__ y, float* __restrict__ mp_out) {
    int r = (blockIdx.x*blockDim.x + threadIdx.x) >> 5;
    int lane = threadIdx.x & 31;
    if (r >= NE) return;
    float acc[7];
    #pragma unroll
    for (int u = 0; u < 7; u++) acc[u] = 0.f;
    int s = rowptr[r], e = rowptr[r+1];
    for (int idx = s; idx < e; idx++) {
        int c = __ldg(&col[idx]);
        float v = __ldg(&val[idx]);
        const float* xr = x + (size_t)c*DIM;
        #pragma unroll
        for (int u = 0; u < 7; u++) {
            int j = lane + 32*u;
            if (j < 200) acc[u] = fmaf(v, xr[j], acc[u]);
        }
    }
    float m = mask[r];
    const float* xr = x + (size_t)r*DIM;
    float* yr = y + (size_t)r*DIM;
    #pragma unroll
    for (int u = 0; u < 7; u++) {
        int j = lane + 32*u;
        if (j < 200) {
            if (WRITE_MP) mp_out[(size_t)r*DIM + j] = acc[u];
            yr[j] = m*xr[j] + (1.f - m)*acc[u];
        }
    }
}

__global__ void rescal_k(const float* __restrict__ e0, const float* __restrict__ rel_emb,
                         const int* __restrict__ sub, const int* __restrict__ rel,
                         float* __restrict__ hr) {
    int b = blockIdx.x;
    int j = threadIdx.x;
    __shared__ float ls[DIM];
    const float* lhs = e0 + (size_t)sub[b]*DIM;
    if (j < DIM) ls[j] = lhs[j];
    __syncthreads();
    if (j < DIM) {
        const float* R = rel_emb + (size_t)rel[b]*RELD;
        float acc = 0.f;
        #pragma unroll 4
        for (int k = 0; k < DIM; k++) acc = fmaf(ls[k], R[(size_t)k*DIM + j], acc);
        hr[(size_t)b*DIM + j] = acc;
    }
}

// ================= launch ==================================================
extern "C" void kernel_launch(void* const* d_in, const int* in_sizes, int n_in,
                              void* d_out, int out_size) {
    const float* e0       = (const float*)d_in[0];
    const float* rel_emb  = (const float*)d_in[1];
    const float* nW1      = (const float*)d_in[2];
    const float* nb1      = (const float*)d_in[3];
    const float* nW2      = (const float*)d_in[4];
    const float* nb2      = (const float*)d_in[5];
    const float* eW1      = (const float*)d_in[6];
    const float* eb1      = (const float*)d_in[7];
    const float* eW2      = (const float*)d_in[8];
    const float* eb2      = (const float*)d_in[9];
    const int*   adj_row  = (const int*)d_in[10];
    const int*   adj_col  = (const int*)d_in[11];
    const float* adj_val  = (const float*)d_in[12];
    const int*   rw_row   = (const int*)d_in[13];
    const int*   rw_col   = (const int*)d_in[14];
    const float* rw_val   = (const float*)d_in[15];
    const float* node_eps = (const float*)d_in[16];
    const float* edge_eps = (const float*)d_in[17];
    const int*   sub      = (const int*)d_in[18];
    const int*   rel      = (const int*)d_in[19];

    int E   = in_sizes[10];
    int Erw = in_sizes[13];

    float* out        = (float*)d_out;
    float* out_scores = out;
    float* out_xnd    = out + (size_t)BATCH*NE;
    float* out_xed    = out_xnd + (size_t)NE*DIM;

    float *U, *V, *X1, *X2, *MP, *HR, *NMASK, *NEWEDGE;
    int *RPA, *RPR;
    cudaGetSymbolAddress((void**)&U, g_U);
    cudaGetSymbolAddress((void**)&V, g_V);
    cudaGetSymbolAddress((void**)&X1, g_X1);
    cudaGetSymbolAddress((void**)&X2, g_X2);
    cudaGetSymbolAddress((void**)&MP, g_MP);
    cudaGetSymbolAddress((void**)&HR, g_HR);
    cudaGetSymbolAddress((void**)&NMASK, g_NMASK);
    cudaGetSymbolAddress((void**)&NEWEDGE, g_NEWEDGE);
    cudaGetSymbolAddress((void**)&RPA, g_rp_adj);
    cudaGetSymbolAddress((void**)&RPR, g_rp_rw);

    const int SPB  = (NE*32 + 255)/256;
    const int MT   = (NE + 127)/128;      // 391

    // rowptrs + conversions
    rowptr_k<<<(NE+1+255)/256, 256>>>(adj_row, E, RPA);
    rowptr_k<<<(NE+1+255)/256, 256>>>(rw_row, Erw, RPR);
    conv_e0_k<<<(NE*50 + 255)/256, 256>>>(e0);
    dim3 wgrid((DIM*DIM + 255)/256, 4);
    conv_w_k<<<wgrid, 256>>>(nW1, eW1);

    // HMMA GEMM: H0 (X1), H1 (X2), U, V
    dim3 mgrid(MT, 4, 4);
    mm_e0w_k<<<mgrid, 256>>>(nb1, eb1, X1, X2, U, V);

    // gates
    node_gate_k<<<SPB, 256>>>(X1, nW2,       nb2,     node_eps,      NMASK);
    node_gate_k<<<SPB, 256>>>(X2, nW2 + DIM, nb2 + 1, node_eps + NE, NMASK + NE);
    edge_gate_k<<<(E*32 + 255)/256, 256>>>(adj_row, adj_col, adj_val,
                                           eW2 + DIM, eb2 + 1, edge_eps + E, NEWEDGE, E);

    // shared first rw-SpMM + node mix (dual write: MP raw + X1 mixed)
    spmm_mix_k<1><<<SPB, 256>>>(RPR, rw_col, rw_val, e0, NMASK, X1, MP);
    // node-drop branch
    spmm_k<<<SPB, 256>>>(RPA, adj_col, adj_val, X1, X2);
    spmm_mix_k<0><<<SPB, 256>>>(RPR, rw_col, rw_val, X2, NMASK + NE, X1, nullptr);
    spmm_k<<<SPB, 256>>>(RPA, adj_col, adj_val, X1, out_xnd);
    // edge-drop branch (reuses MP = rw@e0)
    spmm_k<<<SPB, 256>>>(RPR, rw_col, rw_val, MP, X1);
    spmm_k<<<SPB, 256>>>(RPA, adj_col, NEWEDGE, X1, out_xed);

    // RESCAL + scores
    rescal_k<<<BATCH, 256>>>(e0, rel_emb, sub, rel, HR);
    conv_hr_k<<<(BATCH*50 + 255)/256, 256>>>(HR);
    dim3 sgrid((NE + 63)/64, BATCH/128);
    scores_mm_k<<<sgrid, 256>>>(out_scores);
}